// round 14
// baseline (speedup 1.0000x reference)
#include <cuda_runtime.h>
#include <cstdint>
#include <math.h>

#define T_STEPS 512
#define BATCH   64
#define IN0     256
#define HID     512
#define NBLK    128
#define NTHR    256

// -------- static device scratch --------
// g_hs2 slot u holds layer0 h_u (u=0 init; u>=1 is hs0[u-1]); slot u written at l0 step u-1
__device__ float g_hs2[(size_t)(T_STEPS + 1) * HID * BATCH];
__device__ float g_xT[(size_t)T_STEPS * IN0 * BATCH];     // inputs transposed [t][k][64]
__device__ float g_hT1[2 * HID * BATCH];                  // layer1 double-buffered h
__device__ unsigned g_p0[16];
__device__ unsigned g_p1[16];
__device__ unsigned g_fb, g_fb_base;

// -------- packed f32x2 helpers --------
__device__ __forceinline__ unsigned long long dupf(float v) {
    unsigned long long r;
    asm("mov.b64 %0, {%1, %1};" : "=l"(r) : "f"(v));
    return r;
}
__device__ __forceinline__ void fma2(unsigned long long &d, unsigned long long a, unsigned long long b) {
    asm("fma.rn.f32x2 %0, %1, %2, %0;" : "+l"(d) : "l"(a), "l"(b));
}
__device__ __forceinline__ float sigf(float x) { return 1.0f / (1.0f + __expf(-x)); }
__device__ __forceinline__ float tanh_fast(float x) {
    float ax = fabsf(x);
    float e  = __expf(-2.0f * ax);
    float r  = __fdividef(1.0f - e, 1.0f + e);
    return copysignf(r, x);
}

// -------- sync primitives --------
__device__ __forceinline__ void arrive(unsigned* ctr) {
    asm volatile("red.release.gpu.global.add.u32 [%0], 1;" :: "l"(ctr) : "memory");
}
__device__ __forceinline__ void wait_ge(const unsigned* ctr, unsigned target) {
    unsigned v;
    do {
        asm volatile("ld.acquire.gpu.global.u32 %0, [%1];" : "=r"(v) : "l"(ctr) : "memory");
    } while ((int)(v - target) < 0);
}
// target for "all 128 blocks completed arrive for step u" on 16-deep slot ring
__device__ __forceinline__ unsigned tgt(int u) {
    return 128u * ((unsigned)(u >> 4) + 1u) - (((u & 15) == 0) ? 128u : 0u);
}
__device__ __forceinline__ void full_barrier(unsigned &expect) {
    __syncthreads();
    if (threadIdx.x == 0) {
        arrive(&g_fb);
        expect += NBLK;
        wait_ge(&g_fb, expect);
    }
    __syncthreads();
}

// -------- cp.async --------
__device__ __forceinline__ void cp16(uint32_t sm, const float* g) {
    asm volatile("cp.async.cg.shared.global [%0], [%1], 16;" :: "r"(sm), "l"(g));
}
__device__ __forceinline__ void cp_commit() { asm volatile("cp.async.commit_group;" ::: "memory"); }
template<int N>
__device__ __forceinline__ void cp_wait() { asm volatile("cp.async.wait_group %0;" :: "n"(N) : "memory"); }

// one chunk = 64 k x 64 b = 4096 floats (16KB), contiguous; 4 cp16 per thread
__device__ __forceinline__ void issue_chunk(float* smdst, const float* src, int tid) {
    uint32_t s = (uint32_t)__cvta_generic_to_shared(smdst);
#pragma unroll
    for (int q = 0; q < 4; ++q) {
        int i4 = tid + q * NTHR;
        cp16(s + i4 * 16, src + i4 * 4);
    }
    cp_commit();
}

// smem layout (floats):
//  w0   [768 k][16 rows]   = 12288
//  w1   [1024 k][16 rows]  = 16384
//  hbuf 6 x [64 k][64 b]   = 24576
//  red  [64 u64 rows][33]  = 4224 floats (one batch-half of partials)
//  bias [32]  (l0: 0..15, l1: 16..31)
#define OFF_W0   0
#define OFF_W1   12288
#define OFF_HBUF 28672
#define OFF_RED  53248
#define OFF_BIAS 57472
#define SMEM_FLOATS 57504   // 230016 bytes

// -------- inner chunk compute: 8 kk per warp slice, tile 4 row-pairs x 4 batch --------
// hb = slot + kc*8*64 + bp*4 ; wp = w + (k0 + kc*8)*16 + rg*8
__device__ __forceinline__ void compute_chunk8(const float* hb, const float* wp,
                                               unsigned long long acc[16])
{
#pragma unroll
    for (int kk = 0; kk < 8; ++kk) {
        float4     h4 = *(const float4*)(hb + kk * 64);
        ulonglong2 wA = *(const ulonglong2*)(wp + kk * 16);
        ulonglong2 wB = *(const ulonglong2*)(wp + kk * 16 + 4);

        unsigned long long hd0 = dupf(h4.x), hd1 = dupf(h4.y),
                           hd2 = dupf(h4.z), hd3 = dupf(h4.w);

        fma2(acc[ 0], wA.x, hd0); fma2(acc[ 1], wA.x, hd1); fma2(acc[ 2], wA.x, hd2); fma2(acc[ 3], wA.x, hd3);
        fma2(acc[ 4], wA.y, hd0); fma2(acc[ 5], wA.y, hd1); fma2(acc[ 6], wA.y, hd2); fma2(acc[ 7], wA.y, hd3);
        fma2(acc[ 8], wB.x, hd0); fma2(acc[ 9], wB.x, hd1); fma2(acc[10], wB.x, hd2); fma2(acc[11], wB.x, hd3);
        fma2(acc[12], wB.y, hd0); fma2(acc[13], wB.y, hd1); fma2(acc[14], wB.y, hd2); fma2(acc[15], wB.y, hd3);
    }
}

__global__ void __launch_bounds__(NTHR, 1)
lstm_fused_kernel(const float* __restrict__ h0,
                  const float* __restrict__ c0,
                  const float* __restrict__ w_ih0, const float* __restrict__ w_hh0,
                  const float* __restrict__ b_ih0, const float* __restrict__ b_hh0,
                  const float* __restrict__ w_ih1, const float* __restrict__ w_hh1,
                  const float* __restrict__ b_ih1, const float* __restrict__ b_hh1,
                  float* __restrict__ out)
{
    extern __shared__ float smem[];
    float* w0_s  = smem + OFF_W0;
    float* w1_s  = smem + OFF_W1;
    float* hbuf  = smem + OFF_HBUF;
    float* red_f = smem + OFF_RED;
    unsigned long long* red_u = (unsigned long long*)red_f;
    float* bias_s = smem + OFF_BIAS;

    const int tid = threadIdx.x;
    const int hg  = blockIdx.x;              // hidden group: 4 units per layer

    // compute roles
    const int kc = tid >> 5;                 // 0..7  warp = split-K
    const int rg = (tid >> 4) & 1;           // 0..1  row-half (4 pairs each)
    const int bp = tid & 15;                 // 0..15 (4 batch each)

    // cell roles: one cell per layer per thread
    const int jj = tid >> 6;                 // 0..3 unit in group
    const int b  = tid & 63;                 // batch
    const int bhalf = (b >= 32) ? 1 : 0;     // warp-uniform

    unsigned fb_expect = g_fb_base;

    // ---- init ----
    full_barrier(fb_expect);
    if (tid < 16) { g_p0[tid] = 0; g_p1[tid] = 0; }

    // weights: rows rr = gate*4 + u, global row = gate*HID + hg*4 + u
#pragma unroll 1
    for (int rr = 0; rr < 16; ++rr) {
        int row = (rr >> 2) * HID + hg * 4 + (rr & 3);
        for (int kg = tid; kg < IN0 + HID; kg += NTHR) {
            float v = (kg < IN0) ? w_ih0[row * IN0 + kg]
                                 : w_hh0[row * HID + (kg - IN0)];
            w0_s[kg * 16 + rr] = v;
        }
        for (int kg = tid; kg < 2 * HID; kg += NTHR) {
            float v = (kg < HID) ? w_ih1[row * HID + kg]
                                 : w_hh1[row * HID + (kg - HID)];
            w1_s[kg * 16 + rr] = v;
        }
    }
    if (tid < 16) {
        int row = (tid >> 2) * HID + hg * 4 + (tid & 3);
        bias_s[tid]      = b_ih0[row] + b_hh0[row];
        bias_s[16 + tid] = b_ih1[row] + b_hh1[row];
    }
    float c0_reg, c1_reg;
    {
        int j = hg * 4 + jj;
        c0_reg = c0[b * HID + j];
        c1_reg = c0[BATCH * HID + b * HID + j];
        g_hs2[j * 64 + b] = h0[b * HID + j];                       // l0 h_0 -> slot 0
        g_hT1[j * 64 + b] = h0[BATCH * HID + b * HID + j];         // l1 h_0 -> buf 0
    }
    full_barrier(fb_expect);

    // prefetch superstep-0 groups 0,1 (l0 x chunks 0..3)
    issue_chunk(hbuf + 0 * 4096, g_xT + 0 * 4096, tid);
    issue_chunk(hbuf + 1 * 4096, g_xT + 1 * 4096, tid);
    issue_chunk(hbuf + 2 * 4096, g_xT + 2 * 4096, tid);
    issue_chunk(hbuf + 3 * 4096, g_xT + 3 * 4096, tid);
    // (4 commits in flight = groups 0,1)

    unsigned long long acc[16];
#pragma unroll
    for (int j = 0; j < 16; ++j) acc[j] = 0ull;

    const int hb_off = kc * 8 * 64 + bp * 4;
    const int wp_off = rg * 8;

#pragma unroll 1
    for (int s = 0; s <= T_STEPS; ++s) {
        const bool l0a = (s < T_STEPS);
        const bool l1a = (s >= 1);
        const int  t1  = s - 1;

        const float* xt     = g_xT + (size_t)s * IN0 * 64;                 // l0 x (valid if l0a)
        const float* hs_s   = g_hs2 + (size_t)s * HID * 64;                // l0 h == l1 x (slot s)
        const float* hT1cur = g_hT1 + (size_t)(t1 & 1) * HID * 64;         // l1 h

        const int gstart = l0a ? 0 : 6;
        const int gend   = l1a ? 13 : 5;

        if (!l0a) {
            // s == T_STEPS ramp: need hs2 slot T_STEPS (published by p0[T_STEPS])
            if (tid == 0) wait_ge(&g_p0[s & 15], tgt(s));
            __syncthreads();
            issue_chunk(hbuf + ((12) % 6) * 4096, hs_s + 0 * 4096, tid);
            issue_chunk(hbuf + ((13) % 6) * 4096, hs_s + 1 * 4096, tid);
            issue_chunk(hbuf + ((14) % 6) * 4096, hs_s + 2 * 4096, tid);
            issue_chunk(hbuf + ((15) % 6) * 4096, hs_s + 3 * 4096, tid);
        }

#pragma unroll 1
        for (int g = gstart; g <= gend; ++g) {
            const int gi = g + 2;
            if (gi <= gend) {
                if (gi == 2 && s > 0) {          // first l0-h group: need hs2 slot s
                    if (tid == 0) wait_ge(&g_p0[s & 15], tgt(s));
                    __syncthreads();
                }
                if (gi == 10 && t1 > 0) {        // first l1-h group: need hT1 h_t1
                    if (tid == 0) wait_ge(&g_p1[t1 & 15], tgt(t1));
                    __syncthreads();
                }
                // issue chunks 2*gi, 2*gi+1
#pragma unroll 1
                for (int cc = 2 * gi; cc <= 2 * gi + 1; ++cc) {
                    const float* src;
                    if (cc < 4)       src = xt + (size_t)cc * 4096;
                    else if (cc < 20) src = hs_s + (size_t)((cc - 4) & 7) * 4096;
                    else              src = hT1cur + (size_t)(cc - 20) * 4096;
                    issue_chunk(hbuf + (cc % 6) * 4096, src, tid);
                }
                cp_wait<4>();
            } else if (g + 1 <= gend) {
                cp_wait<2>();
            } else {
                cp_wait<0>();
            }
            __syncthreads();

            // compute group g (chunks 2g, 2g+1)
            {
                int c0c = 2 * g;
                const float* wbase0 = (c0c < 12) ? (w0_s + (size_t)c0c * 64 * 16)
                                                 : (w1_s + (size_t)(c0c - 12) * 64 * 16);
                compute_chunk8(hbuf + (c0c % 6) * 4096 + hb_off, wbase0 + kc * 8 * 16 + wp_off, acc);
                int c1c = c0c + 1;
                const float* wbase1 = (c1c < 12) ? (w0_s + (size_t)c1c * 64 * 16)
                                                 : (w1_s + (size_t)(c1c - 12) * 64 * 16);
                compute_chunk8(hbuf + (c1c % 6) * 4096 + hb_off, wbase1 + kc * 8 * 16 + wp_off, acc);
            }

            // ---- layer0 epilogue after group 5 ----
            if (g == 5) {
                float hn = 0.0f, cn = 0.0f;
#pragma unroll 1
                for (int half = 0; half < 2; ++half) {
                    if ((bp >> 3) == half) {
#pragma unroll
                        for (int p = 0; p < 4; ++p)
#pragma unroll
                            for (int bi = 0; bi < 4; ++bi)
                                red_u[(kc * 8 + rg * 4 + p) * 33 + (bp & 7) * 4 + bi] = acc[p * 4 + bi];
                    }
                    __syncthreads();
                    if (bhalf == half) {
                        float s0 = bias_s[jj], s1 = bias_s[4 + jj], s2 = bias_s[8 + jj], s3 = bias_s[12 + jj];
                        const int lane = (b & 31) * 2 + (jj & 1);
                        const int prh  = jj >> 1;
#pragma unroll
                        for (int k8 = 0; k8 < 8; ++k8) {
                            s0 += red_f[(k8 * 8 +     prh) * 66 + lane];
                            s1 += red_f[(k8 * 8 + 2 + prh) * 66 + lane];
                            s2 += red_f[(k8 * 8 + 4 + prh) * 66 + lane];
                            s3 += red_f[(k8 * 8 + 6 + prh) * 66 + lane];
                        }
                        cn = sigf(s1) * c0_reg + sigf(s0) * tanh_fast(s2);
                        hn = sigf(s3) * tanh_fast(cn);
                        c0_reg = cn;
                        int j = hg * 4 + jj;
                        g_hs2[(size_t)(s + 1) * HID * 64 + j * 64 + b] = hn;
                        if (s == T_STEPS - 1) {
                            out[b * HID + j] = hn;
                            out[2 * BATCH * HID + b * HID + j] = cn;
                        }
                    }
                    __syncthreads();
                }
                if (tid == 0) arrive(&g_p0[(s + 1) & 15]);
#pragma unroll
                for (int j = 0; j < 16; ++j) acc[j] = 0ull;
                if (!l1a) {  // s == 0: prefetch next superstep's A groups here
                    const float* xn = g_xT + (size_t)(s + 1) * IN0 * 64;
                    issue_chunk(hbuf + 0 * 4096, xn + 0 * 4096, tid);
                    issue_chunk(hbuf + 1 * 4096, xn + 1 * 4096, tid);
                    issue_chunk(hbuf + 2 * 4096, xn + 2 * 4096, tid);
                    issue_chunk(hbuf + 3 * 4096, xn + 3 * 4096, tid);
                }
            }
        }

        // ---- layer1 epilogue (after group 13) ----
        if (l1a) {
            // prefetch next superstep's A groups first (slots 0-3 free; x is dep-free)
            if (s < T_STEPS) {
                const float* xn = g_xT + (size_t)(s + 1) * IN0 * 64;
                issue_chunk(hbuf + 0 * 4096, xn + 0 * 4096, tid);
                issue_chunk(hbuf + 1 * 4096, xn + 1 * 4096, tid);
                issue_chunk(hbuf + 2 * 4096, xn + 2 * 4096, tid);
                issue_chunk(hbuf + 3 * 4096, xn + 3 * 4096, tid);
            }
            float hn = 0.0f, cn = 0.0f;
#pragma unroll 1
            for (int half = 0; half < 2; ++half) {
                if ((bp >> 3) == half) {
#pragma unroll
                    for (int p = 0; p < 4; ++p)
#pragma unroll
                        for (int bi = 0; bi < 4; ++bi)
                            red_u[(kc * 8 + rg * 4 + p) * 33 + (bp & 7) * 4 + bi] = acc[p * 4 + bi];
                }
                __syncthreads();
                if (bhalf == half) {
                    float s0 = bias_s[16 + jj], s1 = bias_s[20 + jj], s2 = bias_s[24 + jj], s3 = bias_s[28 + jj];
                    const int lane = (b & 31) * 2 + (jj & 1);
                    const int prh  = jj >> 1;
#pragma unroll
                    for (int k8 = 0; k8 < 8; ++k8) {
                        s0 += red_f[(k8 * 8 +     prh) * 66 + lane];
                        s1 += red_f[(k8 * 8 + 2 + prh) * 66 + lane];
                        s2 += red_f[(k8 * 8 + 4 + prh) * 66 + lane];
                        s3 += red_f[(k8 * 8 + 6 + prh) * 66 + lane];
                    }
                    cn = sigf(s1) * c1_reg + sigf(s0) * tanh_fast(s2);
                    hn = sigf(s3) * tanh_fast(cn);
                    c1_reg = cn;
                    int j = hg * 4 + jj;
                    g_hT1[(size_t)((t1 + 1) & 1) * HID * 64 + j * 64 + b] = hn;
                    if (t1 == T_STEPS - 1) {
                        out[BATCH * HID + b * HID + j] = hn;
                        out[3 * BATCH * HID + b * HID + j] = cn;
                    }
                }
                __syncthreads();
            }
            if (tid == 0) arrive(&g_p1[(t1 + 1) & 15]);
#pragma unroll
            for (int j = 0; j < 16; ++j) acc[j] = 0ull;
        }
    }

    full_barrier(fb_expect);
    if (blockIdx.x == 0 && threadIdx.x == 0)
        g_fb_base = fb_expect;
}

// -------- prepass: transpose inputs to g_xT AND copy passthrough to out tail --------
__global__ void prep_kernel(const float* __restrict__ in, float* __restrict__ out_tail)
{
    __shared__ float tile[32][33];
    int t  = blockIdx.x;
    int i0 = blockIdx.y * 32;
    int b0 = blockIdx.z * 32;
    int tx = threadIdx.x, ty = threadIdx.y;   // 32 x 8
    const float* ip = in + (size_t)t * BATCH * IN0;
    float* cp = out_tail + (size_t)t * BATCH * IN0;
    float* op = g_xT + (size_t)t * IN0 * BATCH;
#pragma unroll
    for (int yy = 0; yy < 32; yy += 8) {
        float v = ip[(b0 + ty + yy) * IN0 + i0 + tx];
        tile[ty + yy][tx] = v;
        cp[(b0 + ty + yy) * IN0 + i0 + tx] = v;
    }
    __syncthreads();
#pragma unroll
    for (int yy = 0; yy < 32; yy += 8)
        op[(i0 + ty + yy) * BATCH + b0 + tx] = tile[tx][ty + yy];
}

extern "C" void kernel_launch(void* const* d_in, const int* in_sizes, int n_in,
                              void* d_out, int out_size)
{
    const float* inputs = (const float*)d_in[0];
    const float* h0     = (const float*)d_in[1];
    const float* c0     = (const float*)d_in[2];
    const float* w_ih0  = (const float*)d_in[3];
    const float* w_hh0  = (const float*)d_in[4];
    const float* b_ih0  = (const float*)d_in[5];
    const float* b_hh0  = (const float*)d_in[6];
    const float* w_ih1  = (const float*)d_in[7];
    const float* w_hh1  = (const float*)d_in[8];
    const float* b_ih1  = (const float*)d_in[9];
    const float* b_hh1  = (const float*)d_in[10];
    float* out = (float*)d_out;

    (void)in_sizes; (void)n_in; (void)out_size;

    cudaFuncSetAttribute(lstm_fused_kernel,
                         cudaFuncAttributeMaxDynamicSharedMemorySize,
                         SMEM_FLOATS * (int)sizeof(float));

    prep_kernel<<<dim3(T_STEPS, IN0 / 32, BATCH / 32), dim3(32, 8)>>>(
        inputs, out + 4 * BATCH * HID);

    lstm_fused_kernel<<<NBLK, NTHR, SMEM_FLOATS * sizeof(float)>>>(
        h0, c0,
        w_ih0, w_hh0, b_ih0, b_hh0,
        w_ih1, w_hh1, b_ih1, b_hh1,
        out);
}

// round 15
// speedup vs baseline: 1.2125x; 1.2125x over previous
#include <cuda_runtime.h>
#include <cstdint>
#include <math.h>

#define T_STEPS 512
#define BATCH   64
#define IN0     256
#define HID     512
#define NBLK    128
#define NTHR    256
#define ROWS    32      // gate rows per block (8 hidden units x 4 gates)

// -------- static device scratch --------
__device__ float g_hs[(size_t)T_STEPS * HID * BATCH];   // layer0 outputs [t][k][64]
__device__ float g_xT[(size_t)T_STEPS * IN0 * BATCH];   // inputs transposed [t][k][64]
__device__ float g_hT[2 * HID * BATCH];                 // double-buffered h [buf][k][64]
__device__ unsigned g_prod[32];    // [bg][slot16]
__device__ unsigned g_fb;
__device__ unsigned g_fb_base;

// -------- packed f32x2 helpers --------
__device__ __forceinline__ unsigned long long dupf(float v) {
    unsigned long long r;
    asm("mov.b64 %0, {%1, %1};" : "=l"(r) : "f"(v));
    return r;
}
__device__ __forceinline__ void fma2(unsigned long long &d, unsigned long long a, unsigned long long b) {
    asm("fma.rn.f32x2 %0, %1, %2, %0;" : "+l"(d) : "l"(a), "l"(b));
}
__device__ __forceinline__ float sigf(float x) { return 1.0f / (1.0f + __expf(-x)); }
__device__ __forceinline__ float tanh_fast(float x) {
    float ax = fabsf(x);
    float e  = __expf(-2.0f * ax);
    float r  = __fdividef(1.0f - e, 1.0f + e);
    return copysignf(r, x);
}

// -------- sync primitives --------
__device__ __forceinline__ void arrive(unsigned* ctr) {
    asm volatile("red.release.gpu.global.add.u32 [%0], 1;" :: "l"(ctr) : "memory");
}
__device__ __forceinline__ void wait_ge(const unsigned* ctr, unsigned target) {
    unsigned v;
    do {
        asm volatile("ld.acquire.gpu.global.u32 %0, [%1];" : "=r"(v) : "l"(ctr) : "memory");
    } while ((int)(v - target) < 0);
}
__device__ __forceinline__ void full_barrier(unsigned &expect) {
    __syncthreads();
    if (threadIdx.x == 0) {
        arrive(&g_fb);
        expect += NBLK;
        wait_ge(&g_fb, expect);
    }
    __syncthreads();
}

// -------- cp.async --------
__device__ __forceinline__ void cp16(uint32_t sm, const float* g) {
    asm volatile("cp.async.cg.shared.global [%0], [%1], 16;" :: "r"(sm), "l"(g));
}
__device__ __forceinline__ void cp_commit() { asm volatile("cp.async.commit_group;" ::: "memory"); }
template<int N>
__device__ __forceinline__ void cp_wait() { asm volatile("cp.async.wait_group %0;" :: "n"(N) : "memory"); }

// one chunk = 128 k x 32 b = 16KB; 4 cp16 per thread (256 threads)
__device__ __forceinline__ void issue_chunk(float* smdst, const float* src, int tid) {
    uint32_t s = (uint32_t)__cvta_generic_to_shared(smdst);
#pragma unroll
    for (int q = 0; q < 4; ++q) {
        int i4 = tid + q * NTHR;          // 0..1023
        int k   = i4 >> 3;                // 0..127
        int off = i4 & 7;                 // 16B units within 128B row
        cp16(s + i4 * 16, src + k * 64 + off * 4);
    }
    cp_commit();
}

// smem layout (floats)
#define OFF_W    0
#define OFF_HBUF 32768
#define OFF_RED  (32768 + 16384)
#define OFF_BIAS (OFF_RED + 8448)
#define SMEM_FLOATS (OFF_BIAS + 32)

// -------- inner chunk compute: 16 kk, tile 4 row-pairs x 4 batch --------
__device__ __forceinline__ void compute_chunk(const float* hb, const float* wp,
                                              unsigned long long acc[16])
{
    float4 h4 = *(const float4*)hb;
    ulonglong2 wA = *(const ulonglong2*)wp;
    ulonglong2 wB = *(const ulonglong2*)(wp + 4);
#pragma unroll
    for (int kk = 0; kk < 16; ++kk) {
        float4     h4n = *(const float4*)(hb + (kk + 1) * 32);
        ulonglong2 wAn = *(const ulonglong2*)(wp + (kk + 1) * 32);
        ulonglong2 wBn = *(const ulonglong2*)(wp + (kk + 1) * 32 + 4);

        unsigned long long hd0 = dupf(h4.x), hd1 = dupf(h4.y),
                           hd2 = dupf(h4.z), hd3 = dupf(h4.w);

        fma2(acc[ 0], wA.x, hd0); fma2(acc[ 1], wA.x, hd1); fma2(acc[ 2], wA.x, hd2); fma2(acc[ 3], wA.x, hd3);
        fma2(acc[ 4], wA.y, hd0); fma2(acc[ 5], wA.y, hd1); fma2(acc[ 6], wA.y, hd2); fma2(acc[ 7], wA.y, hd3);
        fma2(acc[ 8], wB.x, hd0); fma2(acc[ 9], wB.x, hd1); fma2(acc[10], wB.x, hd2); fma2(acc[11], wB.x, hd3);
        fma2(acc[12], wB.y, hd0); fma2(acc[13], wB.y, hd1); fma2(acc[14], wB.y, hd2); fma2(acc[15], wB.y, hd3);

        h4 = h4n; wA = wAn; wB = wBn;
    }
}

template<int K_IN>
__device__ void run_layer(int layer, const float* __restrict__ xT,
                          const float* __restrict__ h0l, const float* __restrict__ c0l,
                          const float* __restrict__ w_ih, const float* __restrict__ w_hh,
                          const float* __restrict__ b_ih, const float* __restrict__ b_hh,
                          float* __restrict__ out, float* smem, unsigned &fb_expect)
{
    constexpr int XC = K_IN / 128;           // x chunks (2 or 4)
    constexpr int K_TOT = K_IN + HID;

    float* w_s   = smem + OFF_W;
    float* hbuf  = smem + OFF_HBUF;
    float* red_f = smem + OFF_RED;
    unsigned long long* red_u = (unsigned long long*)red_f;
    float* bias_s = smem + OFF_BIAS;

    const int tid = threadIdx.x;
    const int bg  = blockIdx.x & 1;          // batch half
    const int hg  = blockIdx.x >> 1;         // hidden group (8 units)

    // compute roles: warp = split-K group
    const int kc = tid >> 5;                 // 0..7
    const int rg = (tid >> 3) & 3;           // 0..3 (row-pair quads)
    const int bp = tid & 7;                  // 0..7 (4-batch groups)

    // epilogue roles: one cell each
    const int jj = tid >> 5;                 // 0..7 hidden unit in group
    const int bl = tid & 31;                 // local batch

    unsigned* prod = g_prod + bg * 16;

    // ---- init ----
    full_barrier(fb_expect);
    if (tid < 32) g_prod[tid] = 0;

#pragma unroll 1
    for (int rr = 0; rr < ROWS; ++rr) {
        int row = (rr >> 3) * HID + hg * 8 + (rr & 7);    // gate*H + j
        for (int kg = tid; kg < K_TOT; kg += NTHR) {
            float v = (kg < K_IN) ? w_ih[row * K_IN + kg]
                                  : w_hh[row * HID + (kg - K_IN)];
            w_s[kg * 32 + rr] = v;
        }
    }
    if (tid < 32) {
        int row = (tid >> 3) * HID + hg * 8 + (tid & 7);
        bias_s[tid] = b_ih[row] + b_hh[row];
    }
    float c_reg;
    {
        int j = hg * 8 + jj, b = bg * 32 + bl;
        c_reg = c0l[b * HID + j];
        g_hT[j * 64 + b] = h0l[b * HID + j];      // buffer 0
    }
    full_barrier(fb_expect);

    const int hb_off = kc * 16 * 32 + bp * 4;

    unsigned long long acc[16], accN[16];
#pragma unroll
    for (int j = 0; j < 16; ++j) { acc[j] = 0ull; accN[j] = 0ull; }

    // ---- prologue: load + compute x(0) into acc ----
    {
        const float* x0 = xT + bg * 32;
#pragma unroll
        for (int c = 0; c < XC; ++c)
            issue_chunk(hbuf + c * 4096, x0 + (size_t)c * 128 * 64, tid);
        cp_wait<0>();
        __syncthreads();
#pragma unroll
        for (int c = 0; c < XC; ++c)
            compute_chunk(hbuf + c * 4096 + hb_off,
                          w_s + (c * 128 + kc * 16) * 32 + rg * 8, acc);
    }

    for (int t = 0; t < T_STEPS; ++t) {
        const bool hasnext = (t + 1 < T_STEPS);
        const float* xn   = xT + (size_t)(t + 1) * K_IN * 64 + bg * 32;
        const float* hcur = g_hT + (t & 1) * HID * 64 + bg * 32;

        if (XC == 4) {
            // ===== layer1 schedule =====
            // 1. issue x(t+1) chunks 0..3 (slots 0..3; previous contents fully consumed+synced)
            if (hasnext) {
#pragma unroll
                for (int c = 0; c < 4; ++c)
                    issue_chunk(hbuf + c * 4096, xn + (size_t)c * 128 * 64, tid);
                // 2. compute x(t+1) pair0 -> accN (covers prod wait)
                cp_wait<2>();
                __syncthreads();
                compute_chunk(hbuf + 0 * 4096 + hb_off, w_s + (0 * 128 + kc * 16) * 32 + rg * 8, accN);
                compute_chunk(hbuf + 1 * 4096 + hb_off, w_s + (1 * 128 + kc * 16) * 32 + rg * 8, accN);
            }
            // 3. prod wait (covered) + unconditional sync (also guards slot 0,1 reuse)
            if (t > 0 && tid == 0) {
                unsigned rounds = (unsigned)(t >> 4) + 1u - (((t & 15) == 0) ? 1u : 0u);
                wait_ge(&prod[t & 15], 64u * rounds);
            }
            __syncthreads();
            // 4. issue hA (h chunks 0,1 -> slots 0,1)
            issue_chunk(hbuf + 0 * 4096, hcur + (size_t)0 * 128 * 64, tid);
            issue_chunk(hbuf + 1 * 4096, hcur + (size_t)1 * 128 * 64, tid);
            // 5. compute x(t+1) pair1 -> accN (covers hA load)
            if (hasnext) {
                cp_wait<2>();
                __syncthreads();
                compute_chunk(hbuf + 2 * 4096 + hb_off, w_s + (2 * 128 + kc * 16) * 32 + rg * 8, accN);
                compute_chunk(hbuf + 3 * 4096 + hb_off, w_s + (3 * 128 + kc * 16) * 32 + rg * 8, accN);
                __syncthreads();   // 5b: guard slots 2,3 reuse by hB
            }
            // 6. issue hB (h chunks 2,3 -> slots 2,3)
            issue_chunk(hbuf + 2 * 4096, hcur + (size_t)2 * 128 * 64, tid);
            issue_chunk(hbuf + 3 * 4096, hcur + (size_t)3 * 128 * 64, tid);
            // 7. compute hA (covers hB load)
            cp_wait<2>();
            __syncthreads();
            compute_chunk(hbuf + 0 * 4096 + hb_off, w_s + (4 * 128 + kc * 16) * 32 + rg * 8, acc);
            compute_chunk(hbuf + 1 * 4096 + hb_off, w_s + (5 * 128 + kc * 16) * 32 + rg * 8, acc);
            // 8. compute hB
            cp_wait<0>();
            __syncthreads();
            compute_chunk(hbuf + 2 * 4096 + hb_off, w_s + (6 * 128 + kc * 16) * 32 + rg * 8, acc);
            compute_chunk(hbuf + 3 * 4096 + hb_off, w_s + (7 * 128 + kc * 16) * 32 + rg * 8, acc);
        } else {
            // ===== layer0 schedule (XC == 2) =====
            // 1. issue x(t+1) chunks 0,1 (slots 0,1)
            if (hasnext) {
                issue_chunk(hbuf + 0 * 4096, xn + (size_t)0 * 128 * 64, tid);
                issue_chunk(hbuf + 1 * 4096, xn + (size_t)1 * 128 * 64, tid);
                // 2. compute x chunk0 -> accN (covers prod wait)
                cp_wait<1>();
                __syncthreads();
                compute_chunk(hbuf + 0 * 4096 + hb_off, w_s + (0 * 128 + kc * 16) * 32 + rg * 8, accN);
            }
            // 3. prod wait + unconditional sync
            if (t > 0 && tid == 0) {
                unsigned rounds = (unsigned)(t >> 4) + 1u - (((t & 15) == 0) ? 1u : 0u);
                wait_ge(&prod[t & 15], 64u * rounds);
            }
            __syncthreads();
            // 4. issue hA (h chunks 0,1 -> slots 2,3)
            issue_chunk(hbuf + 2 * 4096, hcur + (size_t)0 * 128 * 64, tid);
            issue_chunk(hbuf + 3 * 4096, hcur + (size_t)1 * 128 * 64, tid);
            // 5. compute x chunk1 -> accN (covers hA load)
            if (hasnext) {
                cp_wait<2>();
                __syncthreads();
                compute_chunk(hbuf + 1 * 4096 + hb_off, w_s + (1 * 128 + kc * 16) * 32 + rg * 8, accN);
                __syncthreads();   // 5b: guard slots 0,1 reuse by hB
            }
            // 6. issue hB (h chunks 2,3 -> slots 0,1)
            issue_chunk(hbuf + 0 * 4096, hcur + (size_t)2 * 128 * 64, tid);
            issue_chunk(hbuf + 1 * 4096, hcur + (size_t)3 * 128 * 64, tid);
            // 7. compute hA (covers hB load)
            cp_wait<2>();
            __syncthreads();
            compute_chunk(hbuf + 2 * 4096 + hb_off, w_s + (2 * 128 + kc * 16) * 32 + rg * 8, acc);
            compute_chunk(hbuf + 3 * 4096 + hb_off, w_s + (3 * 128 + kc * 16) * 32 + rg * 8, acc);
            // 8. compute hB
            cp_wait<0>();
            __syncthreads();
            compute_chunk(hbuf + 0 * 4096 + hb_off, w_s + (4 * 128 + kc * 16) * 32 + rg * 8, acc);
            compute_chunk(hbuf + 1 * 4096 + hb_off, w_s + (5 * 128 + kc * 16) * 32 + rg * 8, acc);
        }

        // ---- reduction: store packed u64 partials ----
#pragma unroll
        for (int rp = 0; rp < 4; ++rp) {
#pragma unroll
            for (int bi = 0; bi < 4; ++bi)
                red_u[(kc * 16 + rg * 4 + rp) * 33 + bp * 4 + bi] = acc[rp * 4 + bi];
        }
        __syncthreads();

        // ---- gates: 1 cell per thread ----
        float hn, cn;
        {
            float s0 = bias_s[jj], s1 = bias_s[8 + jj], s2 = bias_s[16 + jj], s3 = bias_s[24 + jj];
            const int lane = bl * 2 + (jj & 1);
            const int rphi = jj >> 1;
#pragma unroll
            for (int k8 = 0; k8 < 8; ++k8) {
                s0 += red_f[(k8 * 16 +      rphi) * 66 + lane];
                s1 += red_f[(k8 * 16 +  4 + rphi) * 66 + lane];
                s2 += red_f[(k8 * 16 +  8 + rphi) * 66 + lane];
                s3 += red_f[(k8 * 16 + 12 + rphi) * 66 + lane];
            }
            cn = sigf(s1) * c_reg + sigf(s0) * tanh_fast(s2);
            hn = sigf(s3) * tanh_fast(cn);
            c_reg = cn;
        }

        // ---- write h_{t+1} (safe: prod[t] observed => all h_{t-1} reads done) ----
        {
            int j = hg * 8 + jj, b = bg * 32 + bl;
            g_hT[((t + 1) & 1) * HID * 64 + j * 64 + b] = hn;
            if (layer == 0)
                g_hs[((size_t)t * HID + j) * 64 + b] = hn;
            if (t == T_STEPS - 1) {
                out[layer * BATCH * HID + b * HID + j] = hn;
                out[2 * BATCH * HID + layer * BATCH * HID + b * HID + j] = cn;
            }
        }
        __syncthreads();
        if (tid == 0) arrive(&prod[(t + 1) & 15]);

        // ---- swap accumulators ----
        if (hasnext) {
#pragma unroll
            for (int j = 0; j < 16; ++j) { acc[j] = accN[j]; accN[j] = 0ull; }
        }
    }

    full_barrier(fb_expect);
}

__global__ void __launch_bounds__(NTHR, 1)
lstm_scan_kernel(const float* __restrict__ h0,
                 const float* __restrict__ c0,
                 const float* __restrict__ w_ih0, const float* __restrict__ w_hh0,
                 const float* __restrict__ b_ih0, const float* __restrict__ b_hh0,
                 const float* __restrict__ w_ih1, const float* __restrict__ w_hh1,
                 const float* __restrict__ b_ih1, const float* __restrict__ b_hh1,
                 float* __restrict__ out)
{
    extern __shared__ float smem[];
    unsigned fb_expect = g_fb_base;

    run_layer<IN0>(0, g_xT, h0, c0, w_ih0, w_hh0, b_ih0, b_hh0, out, smem, fb_expect);
    run_layer<HID>(1, g_hs, h0 + BATCH * HID, c0 + BATCH * HID,
                   w_ih1, w_hh1, b_ih1, b_hh1, out, smem, fb_expect);

    if (blockIdx.x == 0 && threadIdx.x == 0)
        g_fb_base = fb_expect;
}

// -------- prepass: transpose inputs to g_xT AND copy passthrough to out tail --------
__global__ void prep_kernel(const float* __restrict__ in, float* __restrict__ out_tail)
{
    __shared__ float tile[32][33];
    int t  = blockIdx.x;
    int i0 = blockIdx.y * 32;
    int b0 = blockIdx.z * 32;
    int tx = threadIdx.x, ty = threadIdx.y;   // 32 x 8
    const float* ip = in + (size_t)t * BATCH * IN0;
    float* cp = out_tail + (size_t)t * BATCH * IN0;
    float* op = g_xT + (size_t)t * IN0 * BATCH;
#pragma unroll
    for (int yy = 0; yy < 32; yy += 8) {
        float v = ip[(b0 + ty + yy) * IN0 + i0 + tx];
        tile[ty + yy][tx] = v;
        cp[(b0 + ty + yy) * IN0 + i0 + tx] = v;
    }
    __syncthreads();
#pragma unroll
    for (int yy = 0; yy < 32; yy += 8)
        op[(i0 + ty + yy) * BATCH + b0 + tx] = tile[tx][ty + yy];
}

extern "C" void kernel_launch(void* const* d_in, const int* in_sizes, int n_in,
                              void* d_out, int out_size)
{
    const float* inputs = (const float*)d_in[0];
    const float* h0     = (const float*)d_in[1];
    const float* c0     = (const float*)d_in[2];
    const float* w_ih0  = (const float*)d_in[3];
    const float* w_hh0  = (const float*)d_in[4];
    const float* b_ih0  = (const float*)d_in[5];
    const float* b_hh0  = (const float*)d_in[6];
    const float* w_ih1  = (const float*)d_in[7];
    const float* w_hh1  = (const float*)d_in[8];
    const float* b_ih1  = (const float*)d_in[9];
    const float* b_hh1  = (const float*)d_in[10];
    float* out = (float*)d_out;

    (void)in_sizes; (void)n_in; (void)out_size;

    cudaFuncSetAttribute(lstm_scan_kernel,
                         cudaFuncAttributeMaxDynamicSharedMemorySize,
                         SMEM_FLOATS * (int)sizeof(float));

    prep_kernel<<<dim3(T_STEPS, IN0 / 32, BATCH / 32), dim3(32, 8)>>>(
        inputs, out + 4 * BATCH * HID);

    lstm_scan_kernel<<<NBLK, NTHR, SMEM_FLOATS * sizeof(float)>>>(
        h0, c0,
        w_ih0, w_hh0, b_ih0, b_hh0,
        w_ih1, w_hh1, b_ih1, b_hh1,
        out);
}